// round 1
// baseline (speedup 1.0000x reference)
#include <cuda_runtime.h>
#include <cstddef>

// TransConv_48077863912017 — stride-2 transposed conv as 4 parity-class
// implicit GEMMs. Round 1: SIMT fp32 tiled-GEMM baseline.
//
// Shapes:
//   x : [32, 128, 64, 64]  NCHW fp32
//   W : [4, 4, 128, 128]   HWIO fp32
//   b : [128]              fp32
//   y : [32, 128, 128, 128] NCHW fp32
//
// Math (derived from lhs_dilation=2, pad=(2,2), k=4, cross-correlation):
//   oh = 2*qh + ph, ow = 2*qw + pw, ph/pw in {0,1}
//   y[n,co,oh,ow] = b[co]
//     + sum_{eh,ew in {0,1}} sum_ci x[n,ci, qh+ph-1+eh, qw+pw-1+ew]
//                                   * W[ph+2*eh, pw+2*ew, ci, co]
//   (zero outside [0,64) input bounds)

#define N_B   32
#define C_IN  128
#define H_IN  64
#define W_IN  64
#define C_OUT 128
#define H_OUT 128
#define W_OUT 128

#define BM 128   // spatial tile: 2 qh rows x 64 qw
#define BN 128   // all output channels
#define BK 16    // K chunk (ci slice within one tap)
#define TM 8
#define TN 8

__global__ __launch_bounds__(256, 2)
void tconv_gemm_kernel(const float* __restrict__ x,
                       const float* __restrict__ Wt,
                       const float* __restrict__ bias,
                       float* __restrict__ out) {
    // blockIdx.x : qh tile (0..31), 2 qh rows each
    // blockIdx.y : batch n (0..31)
    // blockIdx.z : parity class (0..3) -> (ph, pw)
    const int qh0 = blockIdx.x * 2;
    const int n   = blockIdx.y;
    const int par = blockIdx.z;
    const int ph  = par >> 1;
    const int pw  = par & 1;

    __shared__ float As[BK][BM];   // As[k][m] : k = ci-in-chunk, m = spatial
    __shared__ float Bs[BK][BN];   // Bs[k][co]

    const int tid = threadIdx.x;       // 0..255
    const int tx  = tid & 15;          // N (co) micro-tile index
    const int ty  = tid >> 4;          // M (spatial) micro-tile index

    // Loader mapping: 256 threads load 128x16 elems (8 per thread),
    // consecutive tid -> consecutive m (A) / co (B) -> coalesced.
    const int lm  = tid & 127;         // m for A, co for B
    const int lk0 = tid >> 7;          // 0 or 1; k = lk0 + 2*i

    const int mr = lm >> 6;            // which of the 2 qh rows
    const int mq = lm & 63;            // qw

    const float* xn = x + (size_t)n * C_IN * H_IN * W_IN;

    float acc[TM][TN];
    #pragma unroll
    for (int i = 0; i < TM; i++)
        #pragma unroll
        for (int j = 0; j < TN; j++)
            acc[i][j] = 0.0f;

    // K loop: 4 taps x (128 ci / BK) chunks = 32 iterations
    #pragma unroll 1
    for (int kt = 0; kt < 32; kt++) {
        const int tap = kt >> 3;           // 0..3
        const int eh  = tap >> 1;
        const int ew  = tap & 1;
        const int ci0 = (kt & 7) * BK;     // ci base of this chunk
        const int kh  = ph + 2 * eh;
        const int kw  = pw + 2 * ew;

        const int ih = qh0 + mr + ph - 1 + eh;   // input row for this m
        const int iw = mq + pw - 1 + ew;          // input col for this m
        const bool inb = (ih >= 0) & (ih < H_IN) & (iw >= 0) & (iw < W_IN);
        const float* xrow = xn + ((size_t)ih * W_IN + iw);       // + ci*H*W below
        const float* wrow = Wt + ((size_t)(kh * 4 + kw) * C_IN + ci0) * C_OUT + lm;

        __syncthreads();
        #pragma unroll
        for (int i = 0; i < 8; i++) {
            const int k = lk0 + 2 * i;
            As[k][lm] = inb ? xrow[(size_t)(ci0 + k) * (H_IN * W_IN)] : 0.0f;
            Bs[k][lm] = wrow[(size_t)k * C_OUT];
        }
        __syncthreads();

        #pragma unroll
        for (int k = 0; k < BK; k++) {
            float a[TM], bb[TN];
            #pragma unroll
            for (int i = 0; i < TM; i++) a[i] = As[k][ty * TM + i];
            #pragma unroll
            for (int j = 0; j < TN; j++) bb[j] = Bs[k][tx * TN + j];
            #pragma unroll
            for (int i = 0; i < TM; i++)
                #pragma unroll
                for (int j = 0; j < TN; j++)
                    acc[i][j] += a[i] * bb[j];
        }
    }

    // Epilogue: scatter to NCHW output (ow stride 2 within parity class)
    #pragma unroll
    for (int j = 0; j < TN; j++) {
        const int co = tx * TN + j;
        const float bv = bias[co];
        #pragma unroll
        for (int i = 0; i < TM; i++) {
            const int m  = ty * TM + i;
            const int r  = m >> 6;
            const int qw = m & 63;
            const int oh = 2 * (qh0 + r) + ph;
            const int ow = 2 * qw + pw;
            out[(((size_t)n * C_OUT + co) * H_OUT + oh) * W_OUT + ow] =
                acc[i][j] + bv;
        }
    }
}

extern "C" void kernel_launch(void* const* d_in, const int* in_sizes, int n_in,
                              void* d_out, int out_size) {
    const float* x  = (const float*)d_in[0];
    const float* Wt = (const float*)d_in[1];
    const float* b  = (const float*)d_in[2];
    float* out = (float*)d_out;

    dim3 grid(H_IN / 2, N_B, 4);   // 32 qh-tiles x 32 batch x 4 parities
    tconv_gemm_kernel<<<grid, 256>>>(x, Wt, b, out);
}

// round 3
// speedup vs baseline: 2.4831x; 2.4831x over previous
#include <cuda_runtime.h>
#include <cuda_fp16.h>
#include <cstdint>
#include <cstddef>

// TransConv_48077863912017 — stride-2 transposed conv as 4 parity-class
// implicit GEMMs using warp-level mma.sync (fp16 2-pass split, fp32 accum).
//
//   x : [32, 128, 64, 64]  NCHW fp32
//   W : [4, 4, 128, 128]   HWIO fp32
//   b : [128]              fp32
//   y : [32, 128, 128, 128] NCHW fp32
//
//   oh = 2*qh + ph, ow = 2*qw + pw, ph/pw in {0,1}
//   y[n,co,oh,ow] = b[co] + sum_{eh,ew} sum_ci
//       x[n,ci, qh+ph-1+eh, qw+pw-1+ew] * W[ph+2eh, pw+2ew, ci, co]
//
// GEMM per parity class: M=128/CTA (2 qh x 64 qw), N=128 (co), K=512
// (4 taps x 128 ci), chunked K=32, double-buffered smem.
// Precision: A = x split into fp16 hi+lo (2 MMA passes), B = W in fp16.
// Dropped term a*(b - b_hi) -> rel_err ~1.5e-4 < 1e-3.

#define N_B   32
#define C_IN  128
#define H_IN  64
#define W_IN  64
#define C_OUT 128
#define H_OUT 128
#define W_OUT 128

// smem tile: [k (32 rows)][row (128 fp16, 256 B)], XOR swizzle on 16B groups.
// tile = 8192 B; per buffer: A_hi, A_lo, B = 24576 B; double buffered = 48 KB.
#define TILE_B     8192
#define BUF_B      24576
#define A_LO_OFF   8192
#define B_OFF      16384

__device__ __forceinline__ uint32_t smem_u32(const void* p) {
    uint32_t a;
    asm("{ .reg .u64 t; cvta.to.shared.u64 t, %1; cvt.u32.u64 %0, t; }"
        : "=r"(a) : "l"(p));
    return a;
}

__device__ __forceinline__ void st16(uint32_t addr, __half v) {
    asm volatile("st.shared.u16 [%0], %1;"
                 :: "r"(addr), "h"(__half_as_ushort(v)) : "memory");
}

__device__ __forceinline__ void ldsm4t(uint32_t* r, uint32_t addr) {
    asm volatile("ldmatrix.sync.aligned.m8n8.x4.trans.shared.b16 "
                 "{%0,%1,%2,%3}, [%4];"
                 : "=r"(r[0]), "=r"(r[1]), "=r"(r[2]), "=r"(r[3])
                 : "r"(addr));
}

__device__ __forceinline__ void mma16816(float* c, const uint32_t* a,
                                         uint32_t b0, uint32_t b1) {
    asm volatile(
        "mma.sync.aligned.m16n8k16.row.col.f32.f16.f16.f32 "
        "{%0,%1,%2,%3}, {%4,%5,%6,%7}, {%8,%9}, {%0,%1,%2,%3};"
        : "+f"(c[0]), "+f"(c[1]), "+f"(c[2]), "+f"(c[3])
        : "r"(a[0]), "r"(a[1]), "r"(a[2]), "r"(a[3]), "r"(b0), "r"(b1));
}

__global__ void __launch_bounds__(256)
tconv_mma_kernel(const float* __restrict__ x,
                 const float* __restrict__ Wt,
                 const float* __restrict__ bias,
                 float* __restrict__ out)
{
    __shared__ __align__(1024) unsigned char smem[2 * BUF_B];
    const uint32_t sbase = smem_u32(smem);

    const int tid = threadIdx.x;
    const int wid = tid >> 5;
    const int l   = tid & 31;

    const int qh0 = blockIdx.x * 2;
    const int n   = blockIdx.y;
    const int par = blockIdx.z;
    const int ph  = par >> 1;
    const int pw  = par & 1;

    // warp grid: 4 (M) x 2 (N); warp tile 32 x 64
    const int wm = (wid >> 1) * 32;
    const int wn = (wid & 1) * 64;

    // loader mapping
    const int lm    = tid & 127;         // m (A) / co (B)
    const int khalf = (tid >> 7) * 16;   // k base: 0 or 16
    const int r     = lm >> 6;
    const int qw    = lm & 63;

    // ldmatrix lane constants
    const int lx   = l & 7;
    const int a_k  = lx + ((l >> 4) & 1) * 8;   // A: k-high on lanes 16-31
    const int a_or = (l >> 3) & 1;              // A: row-seg +8 on odd octet
    const int b_k  = lx + ((l >> 3) & 1) * 8;   // B: k-high on lanes 8-15,24-31
    const int b_or = (l >> 4) & 1;              // B: col-seg +8 on lanes 16-31

    float acc[2][8][4];
    #pragma unroll
    for (int mt = 0; mt < 2; mt++)
        #pragma unroll
        for (int nt = 0; nt < 8; nt++)
            #pragma unroll
            for (int i = 0; i < 4; i++)
                acc[mt][nt][i] = 0.0f;

    float areg[16], breg[16];

    // ---- chunk loader (LDG fp32) ----
    auto load_chunk = [&](int ch) {
        const int tap = ch >> 2;
        const int ci0 = (ch & 3) * 32;
        const int eh  = tap >> 1;
        const int ew  = tap & 1;
        const int kh  = ph + 2 * eh;
        const int kw  = pw + 2 * ew;
        const int ih  = qh0 + r + ph - 1 + eh;
        const int iw  = qw + pw - 1 + ew;
        const bool inb = ((unsigned)ih < (unsigned)H_IN) &
                         ((unsigned)iw < (unsigned)W_IN);
        const float* xp = x + ((((size_t)n * C_IN + ci0 + khalf) * H_IN + ih)
                               * W_IN + iw);
        const float* wp = Wt + (((size_t)(kh * 4 + kw) * C_IN + ci0 + khalf)
                                * C_OUT) + lm;
        #pragma unroll
        for (int i = 0; i < 16; i++) {
            areg[i] = inb ? __ldg(xp + (size_t)i * (H_IN * W_IN)) : 0.0f;
            breg[i] = __ldg(wp + (size_t)i * C_OUT);
        }
    };

    // ---- store converted chunk to smem buffer p ----
    auto sts_chunk = [&](int p) {
        const uint32_t ab = sbase + p * BUF_B;
        #pragma unroll
        for (int i = 0; i < 16; i++) {
            const int k = khalf + i;
            const uint32_t off = (uint32_t)k * 256u
                + (uint32_t)((((lm >> 3) ^ (i & 7)) << 4) | ((lm & 7) * 2));
            const float av = areg[i];
            const __half hi = __float2half_rn(av);
            const __half lo = __float2half_rn(av - __half2float(hi));
            st16(ab + off, hi);
            st16(ab + A_LO_OFF + off, lo);
            st16(ab + B_OFF + off, __float2half_rn(breg[i]));
        }
    };

    // ---- consume chunk from buffer p ----
    auto mma_chunk = [&](int p) {
        const uint32_t Ah = sbase + p * BUF_B;
        const uint32_t Al = Ah + A_LO_OFF;
        const uint32_t Bb = Ah + B_OFF;
        #pragma unroll
        for (int ks = 0; ks < 2; ks++) {
            const int k0 = ks * 16;
            uint32_t ah[2][4], al[2][4];
            #pragma unroll
            for (int mt = 0; mt < 2; mt++) {
                const uint32_t seg =
                    (uint32_t)((((wm + mt * 16) >> 3) | a_or) ^ lx);
                const uint32_t off =
                    (uint32_t)(k0 + a_k) * 256u + (seg << 4);
                ldsm4t(ah[mt], Ah + off);
                ldsm4t(al[mt], Al + off);
            }
            uint32_t bf[4][4];
            #pragma unroll
            for (int nt2 = 0; nt2 < 4; nt2++) {
                const uint32_t seg =
                    (uint32_t)((((wn + nt2 * 16) >> 3) | b_or) ^ lx);
                const uint32_t off =
                    (uint32_t)(k0 + b_k) * 256u + (seg << 4);
                ldsm4t(bf[nt2], Bb + off);
            }
            #pragma unroll
            for (int mt = 0; mt < 2; mt++)
                #pragma unroll
                for (int nt = 0; nt < 8; nt++) {
                    const uint32_t b0 = bf[nt >> 1][(nt & 1) * 2 + 0];
                    const uint32_t b1 = bf[nt >> 1][(nt & 1) * 2 + 1];
                    mma16816(acc[mt][nt], ah[mt], b0, b1);
                    mma16816(acc[mt][nt], al[mt], b0, b1);
                }
        }
    };

    // ---- pipelined main loop: 16 K-chunks ----
    load_chunk(0);
    #pragma unroll 1
    for (int ch = 0; ch < 16; ch++) {
        sts_chunk(ch & 1);
        __syncthreads();
        if (ch < 15) load_chunk(ch + 1);
        mma_chunk(ch & 1);
    }

    // ---- epilogue: scatter fp32 + bias ----
    float* outn = out + (size_t)n * C_OUT * H_OUT * W_OUT;
    const int mrow = wm + (l >> 2);
    const int col0 = wn + 2 * (l & 3);

    #pragma unroll
    for (int mt = 0; mt < 2; mt++) {
        #pragma unroll
        for (int half = 0; half < 2; half++) {
            const int m  = mrow + mt * 16 + half * 8;
            const int rr = m >> 6;
            const int mq = m & 63;
            const int oh = 2 * (qh0 + rr) + ph;
            const int ow = 2 * mq + pw;
            float* orow = outn + (size_t)oh * W_OUT + ow;
            #pragma unroll
            for (int nt = 0; nt < 8; nt++) {
                const int co = col0 + nt * 8;
                const float b0 = __ldg(bias + co);
                const float b1 = __ldg(bias + co + 1);
                orow[(size_t)co * (H_OUT * W_OUT)] =
                    acc[mt][nt][half * 2 + 0] + b0;
                orow[(size_t)(co + 1) * (H_OUT * W_OUT)] =
                    acc[mt][nt][half * 2 + 1] + b1;
            }
        }
    }
}

extern "C" void kernel_launch(void* const* d_in, const int* in_sizes, int n_in,
                              void* d_out, int out_size) {
    const float* x  = (const float*)d_in[0];
    const float* Wt = (const float*)d_in[1];
    const float* b  = (const float*)d_in[2];
    float* out = (float*)d_out;

    dim3 grid(H_IN / 2, N_B, 4);   // 32 qh-tiles x 32 batch x 4 parities
    tconv_mma_kernel<<<grid, 256>>>(x, Wt, b, out);
}